// round 16
// baseline (speedup 1.0000x reference)
#include <cuda_runtime.h>
#include <cuda_fp16.h>

#define SS 256
#define CC 128
#define HH 4
#define DD 32
#define TT (SS*SS)

typedef unsigned int u32;

// ---------------- global scratch (no allocations allowed) ----------------
#define NQ (SS*HH*SS*DD)   // 8,388,608
__device__ __half g_Q [NQ];                    // Q single fp16 (A operand of QK^T)
__device__ __half g_K [NQ];                    // K single fp16
__device__ __half g_V [NQ];                    // V single fp16
__device__ float  g_G [(size_t)TT*CC];
__device__ __half g_O [(size_t)TT*CC];         // attn output single fp16
__device__ __half g_Wqg_h[2*CC*CC], g_Wqg_l[2*CC*CC];   // weights split
__device__ __half g_Wkv_h[2*CC*CC], g_Wkv_l[2*CC*CC];
__device__ __half g_Wo_h [CC*CC],   g_Wo_l [CC*CC];
// fragment-ordered bias1 permutation: [h][w][c4][i][lane][4]
__device__ float  g_pb1[4*8*8*8*32*4];         // 1 MB

__device__ __forceinline__ void split2h(float v, __half& h, __half& l) {
    h = __float2half_rn(v);
    l = __float2half_rn(v - __half2float(h));
}

__device__ __forceinline__ void mma_f16(float* d, const u32* a, const u32* b) {
    asm volatile(
      "mma.sync.aligned.m16n8k16.row.col.f32.f16.f16.f32 "
      "{%0,%1,%2,%3}, {%4,%5,%6,%7}, {%8,%9}, {%0,%1,%2,%3};\n"
      : "+f"(d[0]), "+f"(d[1]), "+f"(d[2]), "+f"(d[3])
      : "r"(a[0]), "r"(a[1]), "r"(a[2]), "r"(a[3]), "r"(b[0]), "r"(b[1]));
}

__device__ __forceinline__ void ldsm4(u32* r, const void* p) {
    u32 a = (u32)__cvta_generic_to_shared(p);
    asm volatile("ldmatrix.sync.aligned.m8n8.x4.shared.b16 {%0,%1,%2,%3}, [%4];"
                 : "=r"(r[0]), "=r"(r[1]), "=r"(r[2]), "=r"(r[3]) : "r"(a));
}
__device__ __forceinline__ void ldsm2t(u32* r, const void* p) {
    u32 a = (u32)__cvta_generic_to_shared(p);
    asm volatile("ldmatrix.sync.aligned.m8n8.x2.trans.shared.b16 {%0,%1}, [%2];"
                 : "=r"(r[0]), "=r"(r[1]) : "r"(a));
}

// ---------------- merged prep: weights split + bias1 permutation ----------
__global__ void prep_all(const float* __restrict__ wq, const float* __restrict__ wk,
                         const float* __restrict__ wv, const float* __restrict__ wg,
                         const float* __restrict__ wo, const float* __restrict__ bias1) {
    int idx = blockIdx.x * 256 + threadIdx.x;   // 262144 total
    if (idx < CC*CC) {
        int i = idx;
        split2h(wq[i], g_Wqg_h[i],         g_Wqg_l[i]);
        split2h(wg[i], g_Wqg_h[CC*CC + i], g_Wqg_l[CC*CC + i]);
        split2h(wk[i], g_Wkv_h[i],         g_Wkv_l[i]);
        split2h(wv[i], g_Wkv_h[CC*CC + i], g_Wkv_l[CC*CC + i]);
        split2h(wo[i], g_Wo_h[i],          g_Wo_l[i]);
    }
    // bias1 permutation: flat j = mt*16 + rowsel*8 + nt*2 + colpair
    int x    = idx & 3;
    int lane = (idx >> 2) & 31;
    int i4   = (idx >> 7) & 7;
    int c4   = (idx >> 10) & 7;
    int w    = (idx >> 13) & 7;
    int h    = idx >> 16;
    int j = i4*4 + x;
    int colpair = j & 1;
    int nt      = (j >> 1) & 3;
    int rowsel  = (j >> 3) & 1;
    int mt      = (j >> 4) & 1;
    int g = lane >> 2, tg = lane & 3;
    int q = w*32 + mt*16 + rowsel*8 + g;
    int k = c4*32 + nt*8 + tg*2 + colpair;
    g_pb1[idx] = bias1[((size_t)h*SS + q)*SS + k];
}

// ---------------- fused input projection (fp16 2-term: A single, W split) --
// grid (512, 4): mode = blockIdx.y>>1 (0: q_x->[Wq;Wg], 1: kv_x->[Wk;Wv]),
//                ny = blockIdx.y&1 (N-half).
#define AST 72
#define PROJ_SMEM (3*128*AST*2)   // 55296 B

__global__ void __launch_bounds__(256, 2) proj01(const float* __restrict__ q_x,
                                                 const float* __restrict__ kv_x,
                                                 const float* __restrict__ bg)
{
    extern __shared__ __half sm[];
    __half* As = sm;
    __half* Bh = sm + 128*AST;
    __half* Bl = sm + 2*128*AST;

    const int tid = threadIdx.x;
    const int lane = tid & 31;
    const int w = tid >> 5;
    const int g = lane >> 2;
    const int tg = lane & 3;
    const int wm = w & 3;
    const int wn = w >> 2;
    const int m0 = blockIdx.x * 128;
    const int mode = blockIdx.y >> 1;
    const int ny = blockIdx.y & 1;
    const int n0 = ny * 128;

    const int arow = ((lane >> 3) & 1) * 8 + (lane & 7);
    const int acol = (lane >> 4) * 8;
    const int brow = (lane >> 4) * 8 + (lane & 7);
    const int bcol = ((lane >> 3) & 1) * 8;

    const float* X = mode ? kv_x : q_x;
    const __half* Wh = mode ? g_Wkv_h : g_Wqg_h;
    const __half* Wl = mode ? g_Wkv_l : g_Wqg_l;

    float acc[2][8][4];
#pragma unroll
    for (int a = 0; a < 2; a++)
#pragma unroll
        for (int b = 0; b < 8; b++)
#pragma unroll
            for (int c = 0; c < 4; c++) acc[a][b][c] = 0.f;

    for (int ks = 0; ks < 2; ks++) {
        const int kbase = ks * 64;
#pragma unroll
        for (int i = 0; i < 8; i++) {
            int lin = tid + 256*i;
            int r = lin >> 4;
            int c = (lin & 15) * 4;
            float4 xv = *(const float4*)(X + (size_t)(m0+r)*CC + kbase + c);
            __half2 p01 = __floats2half2_rn(xv.x, xv.y);
            __half2 p23 = __floats2half2_rn(xv.z, xv.w);
            *(u32*)&As[r*AST+c]   = *(u32*)&p01;
            *(u32*)&As[r*AST+c+2] = *(u32*)&p23;
        }
#pragma unroll
        for (int i = 0; i < 16; i++) {
            int lin = tid + 256*i;
            int r = lin >> 5;
            int c = (lin & 31) * 2;
            *(u32*)&Bh[r*AST+c] = *(const u32*)(Wh + (size_t)(n0+r)*CC + kbase + c);
            *(u32*)&Bl[r*AST+c] = *(const u32*)(Wl + (size_t)(n0+r)*CC + kbase + c);
        }
        __syncthreads();

#pragma unroll
        for (int k16 = 0; k16 < 4; k16++) {
            const int k0 = k16 * 16;
            u32 a[2][4];
#pragma unroll
            for (int mt = 0; mt < 2; mt++)
                ldsm4(a[mt], &As[(wm*32 + mt*16 + arow)*AST + k0 + acol]);
#pragma unroll
            for (int np = 0; np < 4; np++) {
                u32 bhf[4], blf[4];
                ldsm4(bhf, &Bh[(wn*64 + np*16 + brow)*AST + k0 + bcol]);
                ldsm4(blf, &Bl[(wn*64 + np*16 + brow)*AST + k0 + bcol]);
#pragma unroll
                for (int half = 0; half < 2; half++) {
                    int nt = 2*np + half;
#pragma unroll
                    for (int mt = 0; mt < 2; mt++) {
                        mma_f16(acc[mt][nt], a[mt], &bhf[half*2]);
                        mma_f16(acc[mt][nt], a[mt], &blf[half*2]);
                    }
                }
            }
        }
        __syncthreads();
    }

    // --- epilogue ---
#pragma unroll
    for (int mt = 0; mt < 2; mt++) {
#pragma unroll
        for (int nt = 0; nt < 8; nt++) {
#pragma unroll
            for (int rr = 0; rr < 2; rr++) {
                int m   = m0 + wm*32 + mt*16 + g + rr*8;
                int col = wn*64 + nt*8 + tg*2;
                float y0 = acc[mt][nt][rr*2+0];
                float y1 = acc[mt][nt][rr*2+1];
                int hh = col >> 5, d = col & 31;
                int si = m >> 8,  j = m & 255;
                size_t idx = (((size_t)si*HH + hh)*SS + j)*DD + d;
                if (mode == 0) {
                    if (ny == 0) {
                        y0 *= 0.17677669529663687f; y1 *= 0.17677669529663687f;
                        *(__half2*)&g_Q[idx] = __floats2half2_rn(y0, y1);
                    } else {
                        float s0 = 1.f/(1.f + __expf(-(y0 + bg[col])));
                        float s1 = 1.f/(1.f + __expf(-(y1 + bg[col+1])));
                        *(float2*)(g_G + (size_t)m*CC + col) = make_float2(s0, s1);
                    }
                } else {
                    __half2 v = __floats2half2_rn(y0, y1);
                    if (ny == 0) *(__half2*)&g_K[idx] = v;
                    else         *(__half2*)&g_V[idx] = v;
                }
            }
        }
    }
}

// ---------------- output projection (fp16 2-term, A = g_O) ----------------
__global__ void __launch_bounds__(256, 2) proj2(const float* __restrict__ bo,
                                                float* __restrict__ outp)
{
    extern __shared__ __half sm[];
    __half* As = sm;
    __half* Bh = sm + 128*AST;
    __half* Bl = sm + 2*128*AST;

    const int tid = threadIdx.x;
    const int lane = tid & 31;
    const int w = tid >> 5;
    const int g = lane >> 2;
    const int tg = lane & 3;
    const int wm = w & 3;
    const int wn = w >> 2;
    const int m0 = blockIdx.x * 128;

    const int arow = ((lane >> 3) & 1) * 8 + (lane & 7);
    const int acol = (lane >> 4) * 8;
    const int brow = (lane >> 4) * 8 + (lane & 7);
    const int bcol = ((lane >> 3) & 1) * 8;

    float acc[2][8][4];
#pragma unroll
    for (int a = 0; a < 2; a++)
#pragma unroll
        for (int b = 0; b < 8; b++)
#pragma unroll
            for (int c = 0; c < 4; c++) acc[a][b][c] = 0.f;

    for (int ks = 0; ks < 2; ks++) {
        const int kbase = ks * 64;
#pragma unroll
        for (int i = 0; i < 16; i++) {
            int lin = tid + 256*i;
            int r = lin >> 5;
            int c = (lin & 31) * 2;
            *(u32*)&As[r*AST+c] = *(const u32*)(g_O + (size_t)(m0+r)*CC + kbase + c);
        }
#pragma unroll
        for (int i = 0; i < 16; i++) {
            int lin = tid + 256*i;
            int r = lin >> 5;
            int c = (lin & 31) * 2;
            *(u32*)&Bh[r*AST+c] = *(const u32*)(g_Wo_h + (size_t)r*CC + kbase + c);
            *(u32*)&Bl[r*AST+c] = *(const u32*)(g_Wo_l + (size_t)r*CC + kbase + c);
        }
        __syncthreads();

#pragma unroll
        for (int k16 = 0; k16 < 4; k16++) {
            const int k0 = k16 * 16;
            u32 a[2][4];
#pragma unroll
            for (int mt = 0; mt < 2; mt++)
                ldsm4(a[mt], &As[(wm*32 + mt*16 + arow)*AST + k0 + acol]);
#pragma unroll
            for (int np = 0; np < 4; np++) {
                u32 bhf[4], blf[4];
                ldsm4(bhf, &Bh[(wn*64 + np*16 + brow)*AST + k0 + bcol]);
                ldsm4(blf, &Bl[(wn*64 + np*16 + brow)*AST + k0 + bcol]);
#pragma unroll
                for (int half = 0; half < 2; half++) {
                    int nt = 2*np + half;
#pragma unroll
                    for (int mt = 0; mt < 2; mt++) {
                        mma_f16(acc[mt][nt], a[mt], &bhf[half*2]);
                        mma_f16(acc[mt][nt], a[mt], &blf[half*2]);
                    }
                }
            }
        }
        __syncthreads();
    }

#pragma unroll
    for (int mt = 0; mt < 2; mt++) {
#pragma unroll
        for (int nt = 0; nt < 8; nt++) {
#pragma unroll
            for (int rr = 0; rr < 2; rr++) {
                int m   = m0 + wm*32 + mt*16 + g + rr*8;
                int col = wn*64 + nt*8 + tg*2;
                float2 o;
                o.x = acc[mt][nt][rr*2+0] + bo[col];
                o.y = acc[mt][nt][rr*2+1] + bo[col+1];
                *(float2*)(outp + (size_t)m*CC + col) = o;
            }
        }
    }
}

// ---------------- attention v9: single-fp16 Q, K, V, P ----------------
#define KST 40
#define ATTN_SMEM (2*256*KST*2 + 256*4)   // 41984 B

__global__ void __launch_bounds__(256, 2) attn_kernel(const float* __restrict__ bias2)
{
    extern __shared__ char smraw[];
    __half* Ksh = (__half*)smraw;                 // [256][KST]
    __half* Vsh = Ksh + 256*KST;                  // [256][KST]  (k rows, d cols)
    float*  b2s = (float*)(Vsh + 256*KST);        // [256]

    const int tid = threadIdx.x, lane = tid & 31, w = tid >> 5;
    const int g = lane >> 2, tg = lane & 3;
    const int h = blockIdx.x, s = blockIdx.y;
    const size_t headBase = ((size_t)s*HH + h) * SS * DD;

    // ---- stage K and V (both coalesced uint4, same layout) ----
    {
        const uint4* kh4 = (const uint4*)(g_K + headBase);
        const uint4* vh4 = (const uint4*)(g_V + headBase);
#pragma unroll
        for (int it = 0; it < 4; it++) {
            int i = tid + it*256;
            int row = i >> 2, q4 = i & 3;
            *(uint4*)&Ksh[row*KST + q4*8] = kh4[i];
            *(uint4*)&Vsh[row*KST + q4*8] = vh4[i];
        }
    }
    b2s[tid] = bias2[(size_t)s*SS + tid];

    // ---- Q fragments (single fp16), overlap staging ----
    const int q0 = w * 32;
    u32 qf[2][2][4];
    {
        const u32* srcH = (const u32*)(g_Q + headBase);
#pragma unroll
        for (int mt = 0; mt < 2; mt++) {
            int r0 = q0 + mt*16 + g, r1 = r0 + 8;
#pragma unroll
            for (int sl2 = 0; sl2 < 2; sl2++) {
                int kc = sl2*8 + tg;
                qf[mt][sl2][0] = srcH[r0*16 + kc];
                qf[mt][sl2][1] = srcH[r1*16 + kc];
                qf[mt][sl2][2] = srcH[r0*16 + kc + 4];
                qf[mt][sl2][3] = srcH[r1*16 + kc + 4];
            }
        }
    }
    __syncthreads();

    float acc[2][4][4];
#pragma unroll
    for (int mt = 0; mt < 2; mt++)
#pragma unroll
        for (int a = 0; a < 4; a++)
#pragma unroll
            for (int b = 0; b < 4; b++) acc[mt][a][b] = 0.f;
    float m_a[2] = {-1e30f, -1e30f}, m_b[2] = {-1e30f, -1e30f};
    float l_a[2] = {0.f, 0.f},       l_b[2] = {0.f, 0.f};

    const int kr = lane & 7, kcb = lane >> 3;
    const int vrow = ((lane >> 3) & 1) * 8 + (lane & 7);   // trans ldsm2 row

    const float4* pb1base = (const float4*)(g_pb1 + ((((size_t)h*8 + w)*8)*8*32 + lane)*4);

#pragma unroll
    for (int c4 = 0; c4 < 8; c4++) {                   // 8 chunks of 32 keys
        const int n0c = c4 * 32;
        const float4* pb = pb1base + (size_t)c4 * 256;
        // ---- QK^T (single-term) ----
        float sc[2][4][4];
#pragma unroll
        for (int mt = 0; mt < 2; mt++)
#pragma unroll
            for (int nt = 0; nt < 4; nt++)
#pragma unroll
                for (int c = 0; c < 4; c++) sc[mt][nt][c] = 0.f;

#pragma unroll
        for (int nt = 0; nt < 4; nt++) {
            int n8 = n0c + nt*8;
            u32 kb[4];
            ldsm4(kb, &Ksh[(n8 + kr)*KST + kcb*8]);
#pragma unroll
            for (int mt = 0; mt < 2; mt++) {
#pragma unroll
                for (int sl2 = 0; sl2 < 2; sl2++) {
                    mma_f16(sc[mt][nt], qf[mt][sl2], &kb[sl2*2]);
                }
            }
        }

        // ---- bias add (fragment-ordered) + per-row max, rescale ----
#pragma unroll
        for (int mt = 0; mt < 2; mt++) {
            float ta = -1e30f, tb = -1e30f;
#pragma unroll
            for (int np = 0; np < 2; np++) {
                float4 fa = pb[(mt*4 + np)*32];
                float4 fb = pb[(mt*4 + 2 + np)*32];
#pragma unroll
                for (int half = 0; half < 2; half++) {
                    int nt = 2*np + half;
                    int c = n0c + nt*8 + tg*2;
                    float2 b2v = *(float2*)&b2s[c];
                    float bax = half ? fa.z : fa.x;
                    float bay = half ? fa.w : fa.y;
                    float bbx = half ? fb.z : fb.x;
                    float bby = half ? fb.w : fb.y;
                    sc[mt][nt][0] += bax + b2v.x;
                    sc[mt][nt][1] += bay + b2v.y;
                    sc[mt][nt][2] += bbx + b2v.x;
                    sc[mt][nt][3] += bby + b2v.y;
                    ta = fmaxf(ta, fmaxf(sc[mt][nt][0], sc[mt][nt][1]));
                    tb = fmaxf(tb, fmaxf(sc[mt][nt][2], sc[mt][nt][3]));
                }
            }
            ta = fmaxf(ta, __shfl_xor_sync(0xffffffffu, ta, 1));
            ta = fmaxf(ta, __shfl_xor_sync(0xffffffffu, ta, 2));
            tb = fmaxf(tb, __shfl_xor_sync(0xffffffffu, tb, 1));
            tb = fmaxf(tb, __shfl_xor_sync(0xffffffffu, tb, 2));

            float mna = fmaxf(m_a[mt], ta), mnb = fmaxf(m_b[mt], tb);
            float sca = __expf(m_a[mt] - mna), scb = __expf(m_b[mt] - mnb);
            m_a[mt] = mna; m_b[mt] = mnb;
            l_a[mt] *= sca; l_b[mt] *= scb;
#pragma unroll
            for (int nd = 0; nd < 4; nd++) {
                acc[mt][nd][0] *= sca; acc[mt][nd][1] *= sca;
                acc[mt][nd][2] *= scb; acc[mt][nd][3] *= scb;
            }
        }

        // ---- fused exp + single-fp16 pack + P·V per k16 ----
#pragma unroll
        for (int s8 = 0; s8 < 2; s8++) {
            u32 ah[2][4];
#pragma unroll
            for (int mt = 0; mt < 2; mt++) {
#pragma unroll
                for (int half = 0; half < 2; half++) {
                    int nt = 2*s8 + half;
                    float p0 = __expf(sc[mt][nt][0] - m_a[mt]);
                    float p1 = __expf(sc[mt][nt][1] - m_a[mt]);
                    float p2 = __expf(sc[mt][nt][2] - m_b[mt]);
                    float p3 = __expf(sc[mt][nt][3] - m_b[mt]);
                    l_a[mt] += p0 + p1;
                    l_b[mt] += p2 + p3;
                    __half2 h01 = __floats2half2_rn(p0, p1);
                    __half2 h23 = __floats2half2_rn(p2, p3);
                    ah[mt][half*2]     = *(u32*)&h01;
                    ah[mt][half*2 + 1] = *(u32*)&h23;
                }
            }
            int kkg = n0c + s8*16;
#pragma unroll
            for (int nd = 0; nd < 4; nd++) {
                u32 vb[2];
                ldsm2t(vb, &Vsh[(kkg + vrow)*KST + nd*8]);
#pragma unroll
                for (int mt = 0; mt < 2; mt++) {
                    mma_f16(acc[mt][nd], ah[mt], vb);
                }
            }
        }
    }

    // ---- reduce row-sums, epilogue: normalize, gate, fp16 store ----
#pragma unroll
    for (int mt = 0; mt < 2; mt++) {
        float la = l_a[mt], lb = l_b[mt];
        la += __shfl_xor_sync(0xffffffffu, la, 1);
        la += __shfl_xor_sync(0xffffffffu, la, 2);
        lb += __shfl_xor_sync(0xffffffffu, lb, 1);
        lb += __shfl_xor_sync(0xffffffffu, lb, 2);
        const float inva = 1.0f / la;
        const float invb = 1.0f / lb;
        const int ta_t = s*SS + q0 + mt*16 + g;
        const int tb_t = ta_t + 8;
#pragma unroll
        for (int nd = 0; nd < 4; nd++) {
            int col = h*DD + nd*8 + tg*2;
            float2 ga = *(const float2*)(g_G + (size_t)ta_t*CC + col);
            float2 gb = *(const float2*)(g_G + (size_t)tb_t*CC + col);
            float o0 = acc[mt][nd][0] * inva * ga.x;
            float o1 = acc[mt][nd][1] * inva * ga.y;
            float o2 = acc[mt][nd][2] * invb * gb.x;
            float o3 = acc[mt][nd][3] * invb * gb.y;
            *(__half2*)&g_O[(size_t)ta_t*CC + col] = __floats2half2_rn(o0, o1);
            *(__half2*)&g_O[(size_t)tb_t*CC + col] = __floats2half2_rn(o2, o3);
        }
    }
}

// ---------------- launch ----------------
extern "C" void kernel_launch(void* const* d_in, const int* in_sizes, int n_in,
                              void* d_out, int out_size)
{
    const float* q_x   = (const float*)d_in[0];
    const float* kv_x  = (const float*)d_in[1];
    const float* bias1 = (const float*)d_in[2];
    const float* bias2 = (const float*)d_in[3];
    const float* bg    = (const float*)d_in[8];
    const float* bo    = (const float*)d_in[10];
    float* out = (float*)d_out;

    cudaFuncSetAttribute(proj01,      cudaFuncAttributeMaxDynamicSharedMemorySize, PROJ_SMEM);
    cudaFuncSetAttribute(proj2,       cudaFuncAttributeMaxDynamicSharedMemorySize, PROJ_SMEM);
    cudaFuncSetAttribute(attn_kernel, cudaFuncAttributeMaxDynamicSharedMemorySize, ATTN_SMEM);

    prep_all<<<1024, 256>>>((const float*)d_in[4], (const float*)d_in[5],
                            (const float*)d_in[6], (const float*)d_in[7],
                            (const float*)d_in[9], bias1);
    proj01<<<dim3(512, 4), 256, PROJ_SMEM>>>(q_x, kv_x, bg);
    attn_kernel<<<dim3(HH, SS), 256, ATTN_SMEM>>>(bias2);
    proj2<<<512, 256, PROJ_SMEM>>>(bo, out);
}